// round 7
// baseline (speedup 1.0000x reference)
#include <cuda_runtime.h>
#include <cuda_pipeline.h>
#include <math.h>

#define T 4096
#define H 128
#define HH (H*H)
#define C 128
#define NC (T/C)   // 32
#define L 2

// ---------------- scratch (device globals; no allocation allowed) ------------
__device__ float g_x[T*H];
__device__ float g_q[T*H];
__device__ float g_k[T*H];
__device__ float g_kT[T*H];      // per-chunk transposed K: [c][k][s_local]
__device__ float g_v[T*H];
__device__ float g_Wt[10*HH];    // transposed weights [k][n]
__device__ float g_kv[NC*HH];    // per-chunk KV tail sums (full, no partials)
__device__ float g_S[NC*HH];     // state before each chunk
__device__ int   g_rloc[T];      // last reset index within chunk (local), -1 if none
__device__ int   g_cs0[NC];      // chunk tail-sum start (local)
__device__ int   g_crst[NC];     // chunk has reset flag

#define SMG ((2*HH + 32*128)*4)             // qkv: W0 + W1 + A tile   (144KB)
#define SMA ((2*HH + 2*32*128)*4)           // attn: bufA + bufB + Q + P (160KB)
#define SMC ((HH + 128*32)*4)               // chunk_kv: K + V slab (80KB)

// ---------------- prep: weight transpose + reset preprocessing ---------------
__global__ void prep_kernel(const float* __restrict__ W_in, const float* __restrict__ W_q,
                            const float* __restrict__ W_k, const float* __restrict__ W_v,
                            const float* __restrict__ W_ff, const float* __restrict__ W_out,
                            const unsigned char* __restrict__ start) {
    int b = blockIdx.x;
    int tid = threadIdx.x;
    if (b < 160) {
        __shared__ float tile[32][33];
        int z = b >> 4, sub = b & 15;
        const float* src;
        switch (z) {
            case 0: src = W_in; break;
            case 1: src = W_q; break;
            case 2: src = W_k; break;
            case 3: src = W_v; break;
            case 4: src = W_q + HH; break;
            case 5: src = W_k + HH; break;
            case 6: src = W_v + HH; break;
            case 7: src = W_ff; break;
            case 8: src = W_ff + HH; break;
            default: src = W_out; break;
        }
        float* dst = g_Wt + z*HH;
        int k0 = (sub >> 2)*32, n0 = (sub & 3)*32;
        int tx = tid & 31, ty = tid >> 5;    // (32,8)
        #pragma unroll
        for (int i = 0; i < 4; i++)
            tile[ty + 8*i][tx] = src[(n0 + ty + 8*i)*H + k0 + tx];
        __syncthreads();
        #pragma unroll
        for (int i = 0; i < 4; i++)
            dst[(k0 + ty + 8*i)*H + n0 + tx] = tile[tx][ty + 8*i];
    } else {
        __shared__ unsigned char f[C];
        int c = b - 160;
        if (tid < C) f[tid] = start[c*C + tid];
        __syncthreads();
        if (tid < C) {
            int r = -1;
            for (int j = tid; j >= 0; --j) { if (f[j]) { r = j; break; } }
            g_rloc[c*C + tid] = r;
            if (tid == C-1) { g_cs0[c] = (r >= 0) ? r : 0; g_crst[c] = (r >= 0) ? 1 : 0; }
        }
    }
}

// ---------------- async-copy helpers -----------------------------------------
__device__ __forceinline__ void cpW(float* Ws, const float* __restrict__ Wt, int tid) {
    #pragma unroll
    for (int it = 0; it < 16; it++) {
        int idx = (tid + it*256) * 4;
        __pipeline_memcpy_async(Ws + idx, Wt + idx, 16);
    }
}
__device__ __forceinline__ void cpA(float* As, const float* __restrict__ A, int tid) {
    #pragma unroll
    for (int it = 0; it < 4; it++) {
        int idx = (tid + it*256) * 4;
        __pipeline_memcpy_async(As + idx, A + idx, 16);
    }
}

// ---------------- shared GEMM microkernel ------------------------------------
__device__ __forceinline__ void mm32(float acc[4][4], const float* As, const float* Ws,
                                     int gt, int gs) {
    #pragma unroll
    for (int i = 0; i < 4; i++)
        #pragma unroll
        for (int j = 0; j < 4; j++) acc[i][j] = 0.f;
    #pragma unroll 16
    for (int k = 0; k < 128; k++) {
        float4 w = *(const float4*)&Ws[k*128 + gs*4];
        #pragma unroll
        for (int i = 0; i < 4; i++) {
            float a = As[(gt*4+i)*128 + k];
            acc[i][0] += a*w.x; acc[i][1] += a*w.y;
            acc[i][2] += a*w.z; acc[i][3] += a*w.w;
        }
    }
}

__device__ __forceinline__ float phi_f(float v) {
    return (v > 0.f) ? (1.f + v) : __expf(v);
}

// ---------------- fused [map_in] + QKV (cp.async double-buffered W) ----------
template<int FIRST>
__global__ __launch_bounds__(256) void qkv_kernel(const float* __restrict__ A0,
        const float* __restrict__ Wt_in, const float* __restrict__ b_in,
        const float* __restrict__ Wtq, const float* __restrict__ Wtk,
        const float* __restrict__ Wtv) {
    extern __shared__ float sm[];
    float* W0 = sm;               // [k][n] 128x128
    float* W1 = sm + HH;
    float* As = sm + 2*HH;        // [r][k] 32x128
    int tid = threadIdx.x;
    int t0 = blockIdx.x * 32;
    int gt = tid >> 5, gs = tid & 31;

    cpA(As, A0 + t0*H, tid);
    cpW(W0, FIRST ? Wt_in : Wtq, tid);
    __pipeline_commit();                       // g0: A + first W
    cpW(W1, FIRST ? Wtq : Wtk, tid);
    __pipeline_commit();                       // g1
    __pipeline_wait_prior(1);
    __syncthreads();

    if (FIRST) {   // x = emb @ W_in^T + b_in  (keep in As, write g_x)
        float acc[4][4];
        mm32(acc, As, W0, gt, gs);
        __syncthreads();                       // all reads of As/W0 done
        cpW(W0, Wtk, tid);
        __pipeline_commit();                   // g2: Wk -> W0
        float4 bb = *(const float4*)&b_in[gs*4];
        #pragma unroll
        for (int i = 0; i < 4; i++) {
            float4 r = make_float4(acc[i][0]+bb.x, acc[i][1]+bb.y,
                                   acc[i][2]+bb.z, acc[i][3]+bb.w);
            *(float4*)&As[(gt*4+i)*128 + gs*4] = r;
            *(float4*)&g_x[(t0 + gt*4+i)*H + gs*4] = r;
        }
        __pipeline_wait_prior(1);              // g1 (Wq in W1) done
        __syncthreads();
        {   // q = phi(x @ Wq^T)   [W1]
            float acc2[4][4];
            mm32(acc2, As, W1, gt, gs);
            #pragma unroll
            for (int i = 0; i < 4; i++)
                *(float4*)&g_q[(t0 + gt*4+i)*H + gs*4] =
                    make_float4(phi_f(acc2[i][0]), phi_f(acc2[i][1]),
                                phi_f(acc2[i][2]), phi_f(acc2[i][3]));
        }
        __syncthreads();                       // W1 free
        cpW(W1, Wtv, tid);
        __pipeline_commit();                   // g3: Wv -> W1
        __pipeline_wait_prior(1);              // g2 (Wk in W0) done
        __syncthreads();
        {   // k = phi(x @ Wk^T)   [W0]
            float acc2[4][4];
            mm32(acc2, As, W0, gt, gs);
            #pragma unroll
            for (int i = 0; i < 4; i++) {
                int t = t0 + gt*4 + i;
                float r[4] = {phi_f(acc2[i][0]), phi_f(acc2[i][1]),
                              phi_f(acc2[i][2]), phi_f(acc2[i][3])};
                *(float4*)&g_k[t*H + gs*4] = make_float4(r[0],r[1],r[2],r[3]);
                int cc = t >> 7, sl = t & 127;
                float* kT = g_kT + cc*HH + sl;
                #pragma unroll
                for (int j = 0; j < 4; j++) kT[(gs*4+j)*128] = r[j];
            }
        }
        __pipeline_wait_prior(0);              // g3 (Wv in W1) done
        __syncthreads();
        {   // v = x @ Wv^T        [W1]
            float acc2[4][4];
            mm32(acc2, As, W1, gt, gs);
            #pragma unroll
            for (int i = 0; i < 4; i++)
                *(float4*)&g_v[(t0 + gt*4+i)*H + gs*4] =
                    make_float4(acc2[i][0], acc2[i][1], acc2[i][2], acc2[i][3]);
        }
    } else {
        {   // q = phi(x @ Wq^T)   [W0]
            float acc[4][4];
            mm32(acc, As, W0, gt, gs);
            #pragma unroll
            for (int i = 0; i < 4; i++)
                *(float4*)&g_q[(t0 + gt*4+i)*H + gs*4] =
                    make_float4(phi_f(acc[i][0]), phi_f(acc[i][1]),
                                phi_f(acc[i][2]), phi_f(acc[i][3]));
        }
        __syncthreads();                       // W0 free
        cpW(W0, Wtv, tid);
        __pipeline_commit();                   // g2: Wv -> W0
        __pipeline_wait_prior(1);              // g1 (Wk in W1) done
        __syncthreads();
        {   // k = phi(x @ Wk^T)   [W1]
            float acc[4][4];
            mm32(acc, As, W1, gt, gs);
            #pragma unroll
            for (int i = 0; i < 4; i++) {
                int t = t0 + gt*4 + i;
                float r[4] = {phi_f(acc[i][0]), phi_f(acc[i][1]),
                              phi_f(acc[i][2]), phi_f(acc[i][3])};
                *(float4*)&g_k[t*H + gs*4] = make_float4(r[0],r[1],r[2],r[3]);
                int cc = t >> 7, sl = t & 127;
                float* kT = g_kT + cc*HH + sl;
                #pragma unroll
                for (int j = 0; j < 4; j++) kT[(gs*4+j)*128] = r[j];
            }
        }
        __pipeline_wait_prior(0);              // g2 (Wv in W0) done
        __syncthreads();
        {   // v = x @ Wv^T        [W0]
            float acc[4][4];
            mm32(acc, As, W0, gt, gs);
            #pragma unroll
            for (int i = 0; i < 4; i++)
                *(float4*)&g_v[(t0 + gt*4+i)*H + gs*4] =
                    make_float4(acc[i][0], acc[i][1], acc[i][2], acc[i][3]);
        }
    }
}

// ---------------- per-chunk KV tail: block = (chunk, v-column-quarter) --------
// out[kk][q*32+vv] = sum_{s>=s0} K[s][kk] * V[s][q*32+vv]
__global__ __launch_bounds__(256) void chunk_kv_kernel() {
    extern __shared__ float sm[];
    float* Ks = sm;            // [s][kk] 128x128
    float* Vs = sm + HH;       // [s][vv] 128x32
    int bx = blockIdx.x;
    int c = bx >> 2, qi = bx & 3;
    int s0 = g_cs0[c];
    int tid = threadIdx.x;
    int cbase = c * C;
    {
        const float4* K4 = (const float4*)(g_k + cbase*H);
        float4* Ks4 = (float4*)Ks;
        #pragma unroll
        for (int it = 0; it < 16; it++) {
            int idx = tid + it*256;
            int srow = idx >> 5;
            float4 kv4 = K4[idx];
            if (srow < s0) kv4 = make_float4(0.f,0.f,0.f,0.f);
            Ks4[idx] = kv4;
        }
        float4* Vs4 = (float4*)Vs;
        #pragma unroll
        for (int it = 0; it < 4; it++) {
            int idx = tid + it*256;          // 1024 f4 total: row = idx>>3, col4 = idx&7
            int row = idx >> 3, c4 = idx & 7;
            Vs4[idx] = *(const float4*)&g_v[(cbase + row)*H + qi*32 + c4*4];
        }
    }
    __syncthreads();
    int ty = tid >> 3, tx = tid & 7;    // rows ty*4+i (128), cols tx*4+j (32)
    float acc[4][4] = {};
    #pragma unroll 8
    for (int s = 0; s < 128; s++) {
        float4 kf = *(const float4*)&Ks[s*128 + ty*4];
        float4 vf = *(const float4*)&Vs[s*32 + tx*4];
        float kk[4] = {kf.x, kf.y, kf.z, kf.w};
        #pragma unroll
        for (int i = 0; i < 4; i++) {
            acc[i][0] += kk[i]*vf.x; acc[i][1] += kk[i]*vf.y;
            acc[i][2] += kk[i]*vf.z; acc[i][3] += kk[i]*vf.w;
        }
    }
    float* dst = g_kv + c*HH + qi*32;
    #pragma unroll
    for (int i = 0; i < 4; i++)
        *(float4*)&dst[(ty*4+i)*128 + tx*4] =
            make_float4(acc[i][0], acc[i][1], acc[i][2], acc[i][3]);
}

// ---------------- inter-chunk scan: two-level segmented monoid scan ----------
// 128 blocks x 1024 threads. Each element e gets 8 threads, one per 4-chunk segment.
__global__ __launch_bounds__(1024) void scan_kernel() {
    __shared__ float ssum[8][128];
    __shared__ int   srst[8];
    __shared__ int   sc[NC];
    int tid = threadIdx.x;
    int seg = tid >> 7;            // 0..7
    int el  = tid & 127;
    int e   = blockIdx.x * 128 + el;
    if (tid < NC) sc[tid] = g_crst[tid];
    __syncthreads();

    int c0 = seg * 4;
    float kv[4];
    #pragma unroll
    for (int i = 0; i < 4; i++) kv[i] = g_kv[(c0 + i)*HH + e];

    float pre_sum[4];
    int   pre_rst[4];
    float run = 0.f; int rrst = 0;
    #pragma unroll
    for (int i = 0; i < 4; i++) {
        pre_sum[i] = run; pre_rst[i] = rrst;
        int r = sc[c0 + i];
        run = r ? kv[i] : run + kv[i];
        rrst |= r;
    }
    ssum[seg][el] = run;
    if (el == 0) srst[seg] = rrst;
    __syncthreads();

    float base = 0.f;
    #pragma unroll
    for (int j = 0; j < 7; j++) {
        if (j < seg) {
            float as = ssum[j][el];
            base = srst[j] ? as : base + as;
        }
    }
    #pragma unroll
    for (int i = 0; i < 4; i++) {
        float S = pre_rst[i] ? pre_sum[i] : base + pre_sum[i];
        g_S[(c0 + i)*HH + e] = S;
    }
}

// ---------------- fused attn + FF [+ map_out] (double-buffered) ---------------
template<int LAST>
__global__ __launch_bounds__(256) void attn_ff_kernel(
        const float* __restrict__ Wff, const float* __restrict__ bff,
        const float* __restrict__ Wout, const float* __restrict__ bout,
        float* __restrict__ outp) {
    extern __shared__ float sm[];
    float* bufA = sm;              // 128x128: Kt -> S -> Wout
    float* bufB = sm + HH;         // 128x128: V -> Wff
    float* Qs   = sm + 2*HH;       // [t][k] 32x128
    float* P    = Qs + 32*128;     // [t][s] 32x128 (later z tile)
    __shared__ float den_s[32];
    __shared__ int rl_s[32];

    int bx = blockIdx.x;
    int c  = bx >> 2;
    int tb = (bx & 3) * 32;
    int cbase = c * C;
    int tid = threadIdx.x;
    int gt = tid >> 5, gs = tid & 31;

    if (tid < 32) rl_s[tid] = g_rloc[cbase + tb + tid];
    cpW(bufA, g_kT + c*HH, tid);
    cpA(Qs, g_q + (cbase + tb)*H, tid);
    __pipeline_commit();                       // g0: Kt + Q
    cpW(bufB, g_v + cbase*H, tid);
    __pipeline_commit();                       // g1: V
    __pipeline_wait_prior(1);
    __syncthreads();

    // Stage A: P[t][s] = q_t . k_s   [bufA = Kt]
    {
        float acc[4][4];
        mm32(acc, Qs, bufA, gt, gs);
        #pragma unroll
        for (int i = 0; i < 4; i++) {
            int t_idx = gt*4 + i;
            int tl = tb + t_idx;
            int rl = rl_s[t_idx];
            int lo = (rl < 0) ? 0 : rl;
            float pr[4];
            #pragma unroll
            for (int j = 0; j < 4; j++) {
                int s = gs*4 + j;
                float val = acc[i][j];
                if (s == tl) den_s[t_idx] = 1e-6f + val;
                pr[j] = (s >= lo && s <= tl) ? val : 0.f;
            }
            *(float4*)&P[t_idx*128 + gs*4] = make_float4(pr[0],pr[1],pr[2],pr[3]);
        }
    }
    __syncthreads();                           // bufA free, P published
    cpW(bufA, g_S + c*HH, tid);
    __pipeline_commit();                       // g2: S -> bufA
    __pipeline_wait_prior(1);                  // g1 (V) done
    __syncthreads();

    float acc[4][4] = {};
    #pragma unroll 16
    for (int s = 0; s < 128; s++) {            // B1: P @ V   [bufB]
        float4 vf = *(const float4*)&bufB[s*128 + gs*4];
        #pragma unroll
        for (int i = 0; i < 4; i++) {
            float p = P[(gt*4+i)*128 + s];
            acc[i][0] += p*vf.x; acc[i][1] += p*vf.y;
            acc[i][2] += p*vf.z; acc[i][3] += p*vf.w;
        }
    }
    __syncthreads();                           // bufB free
    cpW(bufB, Wff, tid);
    __pipeline_commit();                       // g3: Wff -> bufB
    __pipeline_wait_prior(1);                  // g2 (S) done
    __syncthreads();

    {   // B2: + gate * Q @ S   [bufA]
        float u[4];
        #pragma unroll
        for (int i = 0; i < 4; i++) u[i] = (rl_s[gt*4+i] < 0) ? 1.f : 0.f;
        #pragma unroll 16
        for (int k = 0; k < 128; k++) {
            float4 sf = *(const float4*)&bufA[k*128 + gs*4];
            #pragma unroll
            for (int i = 0; i < 4; i++) {
                float q = Qs[(gt*4+i)*128 + k] * u[i];
                acc[i][0] += q*sf.x; acc[i][1] += q*sf.y;
                acc[i][2] += q*sf.z; acc[i][3] += q*sf.w;
            }
        }
    }

    // z = num/den + x  -> P
    #pragma unroll
    for (int i = 0; i < 4; i++) {
        int t_idx = gt*4 + i;
        int tg = cbase + tb + t_idx;
        float d = 1.f / den_s[t_idx];
        float4 xr = *(const float4*)&g_x[tg*H + gs*4];
        float4 r;
        r.x = acc[i][0]*d + xr.x; r.y = acc[i][1]*d + xr.y;
        r.z = acc[i][2]*d + xr.z; r.w = acc[i][3]*d + xr.w;
        *(float4*)&P[t_idx*128 + gs*4] = r;
    }
    __syncthreads();                           // bufA free, z published
    if (LAST) {
        cpW(bufA, Wout, tid);
        __pipeline_commit();                   // g4: Wout -> bufA
        __pipeline_wait_prior(1);              // g3 (Wff) done
    } else {
        __pipeline_wait_prior(0);
    }
    __syncthreads();

    {   // FF: x = leaky(z @ Wff^T + bff)   [bufB]
        float fa[4][4];
        mm32(fa, P, bufB, gt, gs);
        float4 bb = *(const float4*)&bff[gs*4];
        #pragma unroll
        for (int i = 0; i < 4; i++) {
            int tg = cbase + tb + gt*4 + i;
            float r[4] = {fa[i][0]+bb.x, fa[i][1]+bb.y, fa[i][2]+bb.z, fa[i][3]+bb.w};
            #pragma unroll
            for (int j = 0; j < 4; j++) r[j] = (r[j] > 0.f) ? r[j] : 0.01f*r[j];
            float4 rr = make_float4(r[0],r[1],r[2],r[3]);
            *(float4*)&g_x[tg*H + gs*4] = rr;
            if (LAST) *(float4*)&Qs[(gt*4+i)*128 + gs*4] = rr;
        }
    }
    if (LAST) {
        __pipeline_wait_prior(0);              // g4 (Wout) done
        __syncthreads();                       // x tile published in Qs
        float fa[4][4];
        mm32(fa, Qs, bufA, gt, gs);
        float4 bb = *(const float4*)&bout[gs*4];
        #pragma unroll
        for (int i = 0; i < 4; i++) {
            int tg = cbase + tb + gt*4 + i;
            *(float4*)&outp[tg*H + gs*4] =
                make_float4(fa[i][0]+bb.x, fa[i][1]+bb.y, fa[i][2]+bb.z, fa[i][3]+bb.w);
        }
    }
}

// ---------------- launch ------------------------------------------------------
extern "C" void kernel_launch(void* const* d_in, const int* in_sizes, int n_in,
                              void* d_out, int out_size) {
    const float* emb          = (const float*)d_in[0];
    const unsigned char* start= (const unsigned char*)d_in[1];
    const float* W_in         = (const float*)d_in[2];
    const float* b_in         = (const float*)d_in[3];
    const float* W_q          = (const float*)d_in[4];
    const float* W_k          = (const float*)d_in[5];
    const float* W_v          = (const float*)d_in[6];
    const float* W_ff         = (const float*)d_in[7];
    const float* b_ff         = (const float*)d_in[8];
    const float* W_out        = (const float*)d_in[9];
    const float* b_out        = (const float*)d_in[10];
    float* out = (float*)d_out;

    cudaFuncSetAttribute(qkv_kernel<1>, cudaFuncAttributeMaxDynamicSharedMemorySize, SMG);
    cudaFuncSetAttribute(qkv_kernel<0>, cudaFuncAttributeMaxDynamicSharedMemorySize, SMG);
    cudaFuncSetAttribute(attn_ff_kernel<0>, cudaFuncAttributeMaxDynamicSharedMemorySize, SMA);
    cudaFuncSetAttribute(attn_ff_kernel<1>, cudaFuncAttributeMaxDynamicSharedMemorySize, SMA);
    cudaFuncSetAttribute(chunk_kv_kernel, cudaFuncAttributeMaxDynamicSharedMemorySize, SMC);

    float *px, *pWt;
    cudaGetSymbolAddress((void**)&px, g_x);
    cudaGetSymbolAddress((void**)&pWt, g_Wt);

    prep_kernel<<<192, 256>>>(W_in, W_q, W_k, W_v, W_ff, W_out, start);

    // layer 0 (fused map_in)
    qkv_kernel<1><<<T/32, 256, SMG>>>(emb, pWt, b_in,
                                      pWt + 1*HH, pWt + 2*HH, pWt + 3*HH);
    chunk_kv_kernel<<<NC*4, 256, SMC>>>();
    scan_kernel<<<128, 1024>>>();
    attn_ff_kernel<0><<<NC*4, 256, SMA>>>(pWt + 7*HH, b_ff, nullptr, nullptr, nullptr);

    // layer 1 (fused map_out)
    qkv_kernel<0><<<T/32, 256, SMG>>>(px, nullptr, nullptr,
                                      pWt + 4*HH, pWt + 5*HH, pWt + 6*HH);
    chunk_kv_kernel<<<NC*4, 256, SMC>>>();
    scan_kernel<<<128, 1024>>>();
    attn_ff_kernel<1><<<NC*4, 256, SMA>>>(pWt + 8*HH, b_ff + H,
                                          pWt + 9*HH, b_out, out);
}